// round 1
// baseline (speedup 1.0000x reference)
#include <cuda_runtime.h>

#define NG      121
#define NFACE   6
#define NHAND   21
#define NPAIR   126   // 21*6
#define NOBJ    726   // 6*121
#define MAXB    8192

__constant__ int c_face[6][4] = {
    {0,1,2,3},{0,4,2,6},{0,1,4,5},{1,3,5,7},{2,3,6,7},{4,5,6,7}
};

__device__ float g_num[MAXB];
__device__ float g_cnt[MAXB];

__global__ __launch_bounds__(128) void affinity_main(const float* __restrict__ poses)
{
    const int b   = blockIdx.x;
    const int tid = threadIdx.x;
    const float* __restrict__ P = poses + b * 87;

    __shared__ float  s_pose[87];     // 21 hand + 8 obj, xyz
    __shared__ float  s_xx[NHAND];
    __shared__ float4 s_pts[NOBJ];    // x,y,z, yy
    __shared__ float  s_dist[NPAIR];
    __shared__ int    s_arg[NPAIR];

    if (tid < 87) s_pose[tid] = P[tid];
    __syncthreads();

    if (tid < NHAND) {
        float x = s_pose[tid*3], y = s_pose[tid*3+1], z = s_pose[tid*3+2];
        s_xx[tid] = x*x + y*y + z*z;
    }

    const float* O = s_pose + NHAND*3;   // obj corners, 8 x 3

    // Phase A: 726 bilinear face points
    for (int idx = tid; idx < NOBJ; idx += 128) {
        int f  = idx / NG;
        int p  = idx - f * NG;
        int iu = p / 11;
        int iv = p - iu * 11;
        float u = iu * 0.1f;
        float v = iv * 0.1f;
        float w0 = v * (1.0f - u);
        float w1 = v * u;
        float w2 = (1.0f - v) * (1.0f - u);
        float w3 = u * (1.0f - v);
        int c0 = c_face[f][0], c1 = c_face[f][1], c2 = c_face[f][2], c3 = c_face[f][3];
        float x = w0*O[c0*3+0] + w1*O[c1*3+0] + w2*O[c2*3+0] + w3*O[c3*3+0];
        float y = w0*O[c0*3+1] + w1*O[c1*3+1] + w2*O[c2*3+1] + w3*O[c3*3+1];
        float z = w0*O[c0*3+2] + w1*O[c1*3+2] + w2*O[c2*3+2] + w3*O[c3*3+2];
        float yy = x*x + y*y + z*z;
        s_pts[idx] = make_float4(x, y, z, yy);
    }
    __syncthreads();

    // Phase B: per (hand h, face f) min/argmin over 121 points.
    // Thread mapping t = f*21 + h so a warp's lanes share f (broadcast LDS).
    if (tid < NPAIR) {
        int f = tid / NHAND;        // 0..5
        int h = tid - f * NHAND;    // 0..20
        float hx = s_pose[h*3], hy = s_pose[h*3+1], hz = s_pose[h*3+2];
        float xx = s_xx[h];
        const float4* __restrict__ q = s_pts + f * NG;
        float best = 3.402823466e38f;
        int   bp   = 0;
        #pragma unroll 4
        for (int p = 0; p < NG; p++) {
            float4 c = q[p];
            float zz = hx*c.x + hy*c.y + hz*c.z;
            float d2 = fmaf(-2.0f, zz, xx + c.w);   // == (xx+yy) - 2*zz exactly
            float dd = sqrtf(d2 + 1e-6f);
            if (dd < best) { best = dd; bp = p; }   // first strict min == jnp argmin
        }
        s_dist[h*6 + f] = best;                      // flat index = h*6+f
        s_arg [h*6 + f] = bp;
    }
    __syncthreads();

    // Phase C + D on warp 0
    if (tid < 32) {
        // top-10 smallest of 126, stable (tie -> lower flat index)
        float v0[4]; int i0[4];
        #pragma unroll
        for (int k = 0; k < 4; k++) {
            int t = tid + 32*k;
            if (t < NPAIR) { v0[k] = s_dist[t]; i0[k] = t; }
            else           { v0[k] = 3.402823466e38f; i0[k] = 1 << 20; }
        }
        float my_dist = 0.0f; int my_idx = 0;
        #pragma unroll
        for (int r = 0; r < 10; r++) {
            float bv = v0[0]; int bi = i0[0];
            #pragma unroll
            for (int k = 1; k < 4; k++)
                if (v0[k] < bv || (v0[k] == bv && i0[k] < bi)) { bv = v0[k]; bi = i0[k]; }
            #pragma unroll
            for (int off = 16; off; off >>= 1) {
                float ov = __shfl_xor_sync(0xffffffffu, bv, off);
                int   oi = __shfl_xor_sync(0xffffffffu, bi, off);
                if (ov < bv || (ov == bv && oi < bi)) { bv = ov; bi = oi; }
            }
            if (r == tid) { my_dist = bv; my_idx = bi; }
            #pragma unroll
            for (int k = 0; k < 4; k++)
                if (i0[k] == bi) v0[k] = 3.402823466e38f;
        }

        // common geometry (computed redundantly per lane, cheap)
        float p1x = (O[0]  + O[3]  + O[6]  + O[9] ) * 0.25f;
        float p1y = (O[1]  + O[4]  + O[7]  + O[10]) * 0.25f;
        float p1z = (O[2]  + O[5]  + O[8]  + O[11]) * 0.25f;
        float p2x = (O[12] + O[15] + O[18] + O[21]) * 0.25f;
        float p2y = (O[13] + O[16] + O[19] + O[22]) * 0.25f;
        float p2z = (O[14] + O[17] + O[20] + O[23]) * 0.25f;

        float l1 = 0.0f, l2 = 0.0f;
        #pragma unroll
        for (int e = 0; e < 4; e++) {
            int a = e, bb = (e + 1) & 3;
            float dx = O[a*3+0] - O[bb*3+0];
            float dy = O[a*3+1] - O[bb*3+1];
            float dz = O[a*3+2] - O[bb*3+2];
            l1 += sqrtf(dx*dx + dy*dy + dz*dz);
            int a2 = a + 4, b2 = bb + 4;
            dx = O[a2*3+0] - O[b2*3+0];
            dy = O[a2*3+1] - O[b2*3+1];
            dz = O[a2*3+2] - O[b2*3+2];
            l2 += sqrtf(dx*dx + dy*dy + dz*dz);
        }
        l1 *= 0.25f; l2 *= 0.25f;
        float length = (l1 + l2) * 0.5f;
        float thr = length * 0.2f;

        float dvx = p2x - p1x, dvy = p2y - p1y, dvz = p2z - p1z;
        float dvn = sqrtf(dvx*dvx + dvy*dvy + dvz*dvz);
        float dvn_e = dvn + 1e-5f;
        float ndx = dvx / dvn_e, ndy = dvy / dvn_e, ndz = dvz / dvn_e;

        float sx = 0.0f, sy = 0.0f, sz = 0.0f, sc = 0.0f;
        if (tid < 10) {
            int o = my_idx;
            int h = o / 6;
            int f = o - h * 6;
            (void)h;
            int p = s_arg[o];
            float4 cpt = s_pts[f * NG + p];
            float vx = cpt.x - p1x, vy = cpt.y - p1y, vz = cpt.z - p1z;
            float inner = dvx*vx + dvy*vy + dvz*vz;
            float tt = inner / dvn_e;
            float rx = p1x + ndx * tt;
            float ry = p1y + ndy * tt;
            float rz = p1z + ndz * tt;
            float nx = cpt.x - rx, ny = cpt.y - ry, nz = cpt.z - rz;
            float nn = sqrtf(nx*nx + ny*ny + nz*nz) + 1e-5f;
            nx /= nn; ny /= nn; nz /= nn;
            float m = (my_dist < thr) ? 1.0f : 0.0f;
            sx = m * nx; sy = m * ny; sz = m * nz; sc = m;
        }
        #pragma unroll
        for (int off = 16; off; off >>= 1) {
            sx += __shfl_xor_sync(0xffffffffu, sx, off);
            sy += __shfl_xor_sync(0xffffffffu, sy, off);
            sz += __shfl_xor_sync(0xffffffffu, sz, off);
            sc += __shfl_xor_sync(0xffffffffu, sc, off);
        }
        if (tid == 0) {
            // sum_ij m_i m_j (n_i . n_j) = |sum_i m_i n_i|^2 ; mask.sum = (sum m)^2
            g_num[b] = sx*sx + sy*sy + sz*sz;
            g_cnt[b] = sc*sc;
        }
    }
}

__global__ void affinity_reduce(int bs, float* __restrict__ out)
{
    __shared__ float sn[256], sc[256];
    int tid = threadIdx.x;
    float a = 0.0f, c = 0.0f;
    for (int i = tid; i < bs; i += 256) { a += g_num[i]; c += g_cnt[i]; }
    sn[tid] = a; sc[tid] = c;
    __syncthreads();
    for (int s = 128; s; s >>= 1) {
        if (tid < s) { sn[tid] += sn[tid + s]; sc[tid] += sc[tid + s]; }
        __syncthreads();
    }
    if (tid == 0) out[0] = sn[0] / (sc[0] + 1.0f);
}

extern "C" void kernel_launch(void* const* d_in, const int* in_sizes, int n_in,
                              void* d_out, int out_size)
{
    const float* poses = (const float*)d_in[0];
    int bs = in_sizes[0] / 87;
    if (bs > MAXB) bs = MAXB;
    affinity_main<<<bs, 128>>>(poses);
    affinity_reduce<<<1, 256>>>(bs, (float*)d_out);
}

// round 2
// speedup vs baseline: 1.2136x; 1.2136x over previous
#include <cuda_runtime.h>
#include <math_constants.h>

#define NG      121
#define NFACE   6
#define NHAND   21
#define NPAIR   126   // 21*6
#define NOBJ    726   // 6*121
#define MAXB    8192

__constant__ int c_face[6][4] = {
    {0,1,2,3},{0,4,2,6},{0,1,4,5},{1,3,5,7},{2,3,6,7},{4,5,6,7}
};

__device__ float2 g_acc[MAXB];   // (num, cnt) per batch

// Must be bit-identical everywhere it is used (phase B min and phase D argmin).
__device__ __forceinline__ float dist2(float hx, float hy, float hz, float xx, float4 c)
{
    float zz = fmaf(hz, c.z, fmaf(hy, c.y, __fmul_rn(hx, c.x)));
    return fmaf(-2.0f, zz, __fadd_rn(xx, c.w));   // == (xx+yy) - 2*zz exactly
}

__global__ __launch_bounds__(128) void affinity_main(const float* __restrict__ poses)
{
    const int b   = blockIdx.x;
    const int tid = threadIdx.x;
    const int lane = tid & 31;
    const int warp = tid >> 5;
    const float* __restrict__ P = poses + b * 87;

    __shared__ float  s_pose[87];     // 21 hand + 8 obj, xyz
    __shared__ float  s_xx[NHAND];
    __shared__ float4 s_pts[NOBJ];    // x,y,z, yy
    __shared__ float  s_dist[NPAIR];  // sqrt(min d2 + 1e-6), flat = h*6+f
    __shared__ int    s_self[10];     // selected flat indices
    __shared__ float  s_seld[10];     // selected dists
    __shared__ float4 s_cn[10];       // per-contact (m*nx, m*ny, m*nz, m)

    if (tid < 87) s_pose[tid] = P[tid];
    __syncthreads();

    if (tid < NHAND) {
        float x = s_pose[tid*3], y = s_pose[tid*3+1], z = s_pose[tid*3+2];
        s_xx[tid] = x*x + y*y + z*z;
    }

    const float* O = s_pose + NHAND*3;   // obj corners, 8 x 3

    // ---- Phase A: 726 bilinear face points (x,y,z,yy) ----
    for (int idx = tid; idx < NOBJ; idx += 128) {
        int f  = idx / NG;
        int p  = idx - f * NG;
        int iu = p / 11;
        int iv = p - iu * 11;
        float u = iu * 0.1f;
        float v = iv * 0.1f;
        float w0 = v * (1.0f - u);
        float w1 = v * u;
        float w2 = (1.0f - v) * (1.0f - u);
        float w3 = u * (1.0f - v);
        int c0 = c_face[f][0], c1 = c_face[f][1], c2 = c_face[f][2], c3 = c_face[f][3];
        float x = w0*O[c0*3+0] + w1*O[c1*3+0] + w2*O[c2*3+0] + w3*O[c3*3+0];
        float y = w0*O[c0*3+1] + w1*O[c1*3+1] + w2*O[c2*3+1] + w3*O[c3*3+1];
        float z = w0*O[c0*3+2] + w1*O[c1*3+2] + w2*O[c2*3+2] + w3*O[c3*3+2];
        float yy = x*x + y*y + z*z;
        s_pts[idx] = make_float4(x, y, z, yy);
    }
    __syncthreads();

    // ---- Phase B: min over 121 points per (h,f). FMNMX only, no argmin. ----
    // Thread mapping t = f*21 + h so a warp's lanes share f (broadcast LDS).
    if (tid < NPAIR) {
        int f = tid / NHAND;        // 0..5
        int h = tid - f * NHAND;    // 0..20
        float hx = s_pose[h*3], hy = s_pose[h*3+1], hz = s_pose[h*3+2];
        float xx = s_xx[h];
        const float4* __restrict__ q = s_pts + f * NG;
        float best = CUDART_INF_F;
        #pragma unroll 11
        for (int p = 0; p < NG; p++) {
            float d2 = dist2(hx, hy, hz, xx, q[p]);
            best = fminf(best, d2);
        }
        // min(sqrt(d2+eps)) == sqrt(min(d2)+eps) under RN (weak monotonicity)
        s_dist[h*6 + f] = sqrtf(best + 1e-6f);
    }
    __syncthreads();

    // ---- Phase C: stable top-10 of the 126 dists (warp 0) ----
    if (tid < 32) {
        float v0[4]; int i0[4];
        #pragma unroll
        for (int k = 0; k < 4; k++) {
            int t = tid + 32*k;
            if (t < NPAIR) { v0[k] = s_dist[t]; i0[k] = t; }
            else           { v0[k] = CUDART_INF_F; i0[k] = 1 << 20; }
        }
        #pragma unroll
        for (int r = 0; r < 10; r++) {
            float bv = v0[0]; int bi = i0[0];
            #pragma unroll
            for (int k = 1; k < 4; k++)
                if (v0[k] < bv || (v0[k] == bv && i0[k] < bi)) { bv = v0[k]; bi = i0[k]; }
            #pragma unroll
            for (int off = 16; off; off >>= 1) {
                float ov = __shfl_xor_sync(0xffffffffu, bv, off);
                int   oi = __shfl_xor_sync(0xffffffffu, bi, off);
                if (ov < bv || (ov == bv && oi < bi)) { bv = ov; bi = oi; }
            }
            if (r == tid) { s_self[r] = bi; s_seld[r] = bv; }
            #pragma unroll
            for (int k = 0; k < 4; k++)
                if (i0[k] == bi) v0[k] = CUDART_INF_F;
        }
    }
    __syncthreads();

    // ---- Phase D: per-contact argmin recovery + normal contribution ----
    {
        // shared geometry (redundant per lane; cheap)
        float p1x = (O[0]  + O[3]  + O[6]  + O[9] ) * 0.25f;
        float p1y = (O[1]  + O[4]  + O[7]  + O[10]) * 0.25f;
        float p1z = (O[2]  + O[5]  + O[8]  + O[11]) * 0.25f;
        float p2x = (O[12] + O[15] + O[18] + O[21]) * 0.25f;
        float p2y = (O[13] + O[16] + O[19] + O[22]) * 0.25f;
        float p2z = (O[14] + O[17] + O[20] + O[23]) * 0.25f;

        float l1 = 0.0f, l2 = 0.0f;
        #pragma unroll
        for (int e = 0; e < 4; e++) {
            int a = e, bb = (e + 1) & 3;
            float dx = O[a*3+0] - O[bb*3+0];
            float dy = O[a*3+1] - O[bb*3+1];
            float dz = O[a*3+2] - O[bb*3+2];
            l1 += sqrtf(dx*dx + dy*dy + dz*dz);
            int a2 = a + 4, b2 = bb + 4;
            dx = O[a2*3+0] - O[b2*3+0];
            dy = O[a2*3+1] - O[b2*3+1];
            dz = O[a2*3+2] - O[b2*3+2];
            l2 += sqrtf(dx*dx + dy*dy + dz*dz);
        }
        l1 *= 0.25f; l2 *= 0.25f;
        float thr = ((l1 + l2) * 0.5f) * 0.2f;

        float dvx = p2x - p1x, dvy = p2y - p1y, dvz = p2z - p1z;
        float dvn = sqrtf(dvx*dvx + dvy*dvy + dvz*dvz);
        float dvn_e = dvn + 1e-5f;
        float ndx = dvx / dvn_e, ndy = dvy / dvn_e, ndz = dvz / dvn_e;

        for (int c = warp; c < 10; c += 4) {
            int flat = s_self[c];
            float dist = s_seld[c];
            int h = flat / 6;
            int f = flat - h * 6;
            float hx = s_pose[h*3], hy = s_pose[h*3+1], hz = s_pose[h*3+2];
            float xx = s_xx[h];
            const float4* __restrict__ q = s_pts + f * NG;

            float bd = CUDART_INF_F; int bp = NG;
            #pragma unroll
            for (int k = 0; k < 4; k++) {
                int p = k*32 + lane;
                if (p < NG) {
                    float d2 = dist2(hx, hy, hz, xx, q[p]);
                    if (d2 < bd) { bd = d2; bp = p; }   // first occurrence per lane
                }
            }
            #pragma unroll
            for (int off = 16; off; off >>= 1) {
                float ov = __shfl_xor_sync(0xffffffffu, bd, off);
                int   op = __shfl_xor_sync(0xffffffffu, bp, off);
                if (ov < bd || (ov == bd && op < bp)) { bd = ov; bp = op; }
            }
            if (lane == 0) {
                float4 cpt = q[bp];
                float vx = cpt.x - p1x, vy = cpt.y - p1y, vz = cpt.z - p1z;
                float inner = dvx*vx + dvy*vy + dvz*vz;
                float tt = inner / dvn_e;
                float rx = p1x + ndx * tt;
                float ry = p1y + ndy * tt;
                float rz = p1z + ndz * tt;
                float nx = cpt.x - rx, ny = cpt.y - ry, nz = cpt.z - rz;
                float nn = sqrtf(nx*nx + ny*ny + nz*nz) + 1e-5f;
                nx /= nn; ny /= nn; nz /= nn;
                float m = (dist < thr) ? 1.0f : 0.0f;
                s_cn[c] = make_float4(m*nx, m*ny, m*nz, m);
            }
        }
    }
    __syncthreads();

    // ---- Final: sum_ij m_i m_j (n_i.n_j) = |sum m n|^2 ; mask.sum = (sum m)^2 ----
    if (tid < 32) {
        float sx = 0.0f, sy = 0.0f, sz = 0.0f, sc = 0.0f;
        if (tid < 10) {
            float4 v = s_cn[tid];
            sx = v.x; sy = v.y; sz = v.z; sc = v.w;
        }
        #pragma unroll
        for (int off = 16; off; off >>= 1) {
            sx += __shfl_xor_sync(0xffffffffu, sx, off);
            sy += __shfl_xor_sync(0xffffffffu, sy, off);
            sz += __shfl_xor_sync(0xffffffffu, sz, off);
            sc += __shfl_xor_sync(0xffffffffu, sc, off);
        }
        if (tid == 0)
            g_acc[b] = make_float2(sx*sx + sy*sy + sz*sz, sc*sc);
    }
}

__global__ __launch_bounds__(1024) void affinity_reduce(int bs, float* __restrict__ out)
{
    __shared__ float2 sh[32];
    int tid = threadIdx.x;
    int lane = tid & 31;
    int warp = tid >> 5;
    float a = 0.0f, c = 0.0f;
    for (int i = tid; i < bs; i += 1024) {
        float2 v = g_acc[i];
        a += v.x; c += v.y;
    }
    #pragma unroll
    for (int off = 16; off; off >>= 1) {
        a += __shfl_xor_sync(0xffffffffu, a, off);
        c += __shfl_xor_sync(0xffffffffu, c, off);
    }
    if (lane == 0) sh[warp] = make_float2(a, c);
    __syncthreads();
    if (tid < 32) {
        float2 v = sh[tid];
        a = v.x; c = v.y;
        #pragma unroll
        for (int off = 16; off; off >>= 1) {
            a += __shfl_xor_sync(0xffffffffu, a, off);
            c += __shfl_xor_sync(0xffffffffu, c, off);
        }
        if (tid == 0) out[0] = a / (c + 1.0f);
    }
}

extern "C" void kernel_launch(void* const* d_in, const int* in_sizes, int n_in,
                              void* d_out, int out_size)
{
    const float* poses = (const float*)d_in[0];
    int bs = in_sizes[0] / 87;
    if (bs > MAXB) bs = MAXB;
    affinity_main<<<bs, 128>>>(poses);
    affinity_reduce<<<1, 1024>>>(bs, (float*)d_out);
}

// round 3
// speedup vs baseline: 1.2790x; 1.0538x over previous
#include <cuda_runtime.h>
#include <math_constants.h>

#define NG      121
#define NFACE   6
#define NHAND   21
#define NPAIR   126   // 21*6
#define NOBJ    726   // 6*121
#define MAXB    8192

__constant__ int c_face[6][4] = {
    {0,1,2,3},{0,4,2,6},{0,1,4,5},{1,3,5,7},{2,3,6,7},{4,5,6,7}
};

__device__ float2 g_acc[MAXB];   // (num, cnt) per batch

// Must be bit-identical everywhere it is used (phase B min and phase D argmin).
__device__ __forceinline__ float dist2(float hx, float hy, float hz, float xx, float4 c)
{
    float zz = fmaf(hz, c.z, fmaf(hy, c.y, __fmul_rn(hx, c.x)));
    return fmaf(-2.0f, zz, __fadd_rn(xx, c.w));   // == (xx+yy) - 2*zz exactly
}

__global__ __launch_bounds__(128) void affinity_main(const float* __restrict__ poses)
{
    const int b   = blockIdx.x;
    const int tid = threadIdx.x;
    const int lane = tid & 31;
    const int warp = tid >> 5;
    const float* __restrict__ P = poses + b * 87;

    __shared__ float  s_pose[87];     // 21 hand + 8 obj, xyz
    __shared__ float  s_xx[NHAND];
    __shared__ float4 s_pts[NOBJ];    // x,y,z, yy
    __shared__ float  s_dist[NPAIR];  // sqrt(min d2 + 1e-6), flat = h*6+f
    __shared__ int    s_self[10];     // selected flat indices
    __shared__ float  s_seld[10];     // selected dists
    __shared__ float4 s_cn[10];       // per-contact (m*nx, m*ny, m*nz, m)

    if (tid < 87) s_pose[tid] = P[tid];
    __syncthreads();

    if (tid < NHAND) {
        float x = s_pose[tid*3], y = s_pose[tid*3+1], z = s_pose[tid*3+2];
        s_xx[tid] = x*x + y*y + z*z;
    }

    const float* O = s_pose + NHAND*3;   // obj corners, 8 x 3

    // ---- Phase A: 726 bilinear face points (x,y,z,yy) ----
    for (int idx = tid; idx < NOBJ; idx += 128) {
        int f  = idx / NG;
        int p  = idx - f * NG;
        int iu = p / 11;
        int iv = p - iu * 11;
        float u = iu * 0.1f;
        float v = iv * 0.1f;
        float w0 = v * (1.0f - u);
        float w1 = v * u;
        float w2 = (1.0f - v) * (1.0f - u);
        float w3 = u * (1.0f - v);
        int c0 = c_face[f][0], c1 = c_face[f][1], c2 = c_face[f][2], c3 = c_face[f][3];
        float x = w0*O[c0*3+0] + w1*O[c1*3+0] + w2*O[c2*3+0] + w3*O[c3*3+0];
        float y = w0*O[c0*3+1] + w1*O[c1*3+1] + w2*O[c2*3+1] + w3*O[c3*3+1];
        float z = w0*O[c0*3+2] + w1*O[c1*3+2] + w2*O[c2*3+2] + w3*O[c3*3+2];
        float yy = x*x + y*y + z*z;
        s_pts[idx] = make_float4(x, y, z, yy);
    }
    __syncthreads();

    // ---- Phase B: min over 121 points per (h,f). FMNMX only, no argmin. ----
    // Thread mapping t = f*21 + h so a warp's lanes share f (broadcast LDS).
    if (tid < NPAIR) {
        int f = tid / NHAND;        // 0..5
        int h = tid - f * NHAND;    // 0..20
        float hx = s_pose[h*3], hy = s_pose[h*3+1], hz = s_pose[h*3+2];
        float xx = s_xx[h];
        const float4* __restrict__ q = s_pts + f * NG;
        float best = CUDART_INF_F;
        #pragma unroll 11
        for (int p = 0; p < NG; p++) {
            float d2 = dist2(hx, hy, hz, xx, q[p]);
            best = fminf(best, d2);
        }
        // min(sqrt(d2+eps)) == sqrt(min(d2)+eps) under RN (weak monotonicity)
        s_dist[h*6 + f] = sqrtf(best + 1e-6f);
    }
    __syncthreads();

    // ---- Phase C: stable top-10 of the 126 dists (warp 0) ----
    if (tid < 32) {
        float v0[4]; int i0[4];
        #pragma unroll
        for (int k = 0; k < 4; k++) {
            int t = tid + 32*k;
            if (t < NPAIR) { v0[k] = s_dist[t]; i0[k] = t; }
            else           { v0[k] = CUDART_INF_F; i0[k] = 1 << 20; }
        }
        #pragma unroll
        for (int r = 0; r < 10; r++) {
            float bv = v0[0]; int bi = i0[0];
            #pragma unroll
            for (int k = 1; k < 4; k++)
                if (v0[k] < bv || (v0[k] == bv && i0[k] < bi)) { bv = v0[k]; bi = i0[k]; }
            #pragma unroll
            for (int off = 16; off; off >>= 1) {
                float ov = __shfl_xor_sync(0xffffffffu, bv, off);
                int   oi = __shfl_xor_sync(0xffffffffu, bi, off);
                if (ov < bv || (ov == bv && oi < bi)) { bv = ov; bi = oi; }
            }
            if (r == tid) { s_self[r] = bi; s_seld[r] = bv; }
            #pragma unroll
            for (int k = 0; k < 4; k++)
                if (i0[k] == bi) v0[k] = CUDART_INF_F;
        }
    }
    __syncthreads();

    // ---- Phase D: per-contact argmin recovery + normal contribution ----
    {
        // shared geometry (redundant per lane; cheap)
        float p1x = (O[0]  + O[3]  + O[6]  + O[9] ) * 0.25f;
        float p1y = (O[1]  + O[4]  + O[7]  + O[10]) * 0.25f;
        float p1z = (O[2]  + O[5]  + O[8]  + O[11]) * 0.25f;
        float p2x = (O[12] + O[15] + O[18] + O[21]) * 0.25f;
        float p2y = (O[13] + O[16] + O[19] + O[22]) * 0.25f;
        float p2z = (O[14] + O[17] + O[20] + O[23]) * 0.25f;

        float l1 = 0.0f, l2 = 0.0f;
        #pragma unroll
        for (int e = 0; e < 4; e++) {
            int a = e, bb = (e + 1) & 3;
            float dx = O[a*3+0] - O[bb*3+0];
            float dy = O[a*3+1] - O[bb*3+1];
            float dz = O[a*3+2] - O[bb*3+2];
            l1 += sqrtf(dx*dx + dy*dy + dz*dz);
            int a2 = a + 4, b2 = bb + 4;
            dx = O[a2*3+0] - O[b2*3+0];
            dy = O[a2*3+1] - O[b2*3+1];
            dz = O[a2*3+2] - O[b2*3+2];
            l2 += sqrtf(dx*dx + dy*dy + dz*dz);
        }
        l1 *= 0.25f; l2 *= 0.25f;
        float thr = ((l1 + l2) * 0.5f) * 0.2f;

        float dvx = p2x - p1x, dvy = p2y - p1y, dvz = p2z - p1z;
        float dvn = sqrtf(dvx*dvx + dvy*dvy + dvz*dvz);
        float dvn_e = dvn + 1e-5f;
        float ndx = dvx / dvn_e, ndy = dvy / dvn_e, ndz = dvz / dvn_e;

        for (int c = warp; c < 10; c += 4) {
            int flat = s_self[c];
            float dist = s_seld[c];
            int h = flat / 6;
            int f = flat - h * 6;
            float hx = s_pose[h*3], hy = s_pose[h*3+1], hz = s_pose[h*3+2];
            float xx = s_xx[h];
            const float4* __restrict__ q = s_pts + f * NG;

            float bd = CUDART_INF_F; int bp = NG;
            #pragma unroll
            for (int k = 0; k < 4; k++) {
                int p = k*32 + lane;
                if (p < NG) {
                    float d2 = dist2(hx, hy, hz, xx, q[p]);
                    if (d2 < bd) { bd = d2; bp = p; }   // first occurrence per lane
                }
            }
            #pragma unroll
            for (int off = 16; off; off >>= 1) {
                float ov = __shfl_xor_sync(0xffffffffu, bd, off);
                int   op = __shfl_xor_sync(0xffffffffu, bp, off);
                if (ov < bd || (ov == bd && op < bp)) { bd = ov; bp = op; }
            }
            if (lane == 0) {
                float4 cpt = q[bp];
                float vx = cpt.x - p1x, vy = cpt.y - p1y, vz = cpt.z - p1z;
                float inner = dvx*vx + dvy*vy + dvz*vz;
                float tt = inner / dvn_e;
                float rx = p1x + ndx * tt;
                float ry = p1y + ndy * tt;
                float rz = p1z + ndz * tt;
                float nx = cpt.x - rx, ny = cpt.y - ry, nz = cpt.z - rz;
                float nn = sqrtf(nx*nx + ny*ny + nz*nz) + 1e-5f;
                nx /= nn; ny /= nn; nz /= nn;
                float m = (dist < thr) ? 1.0f : 0.0f;
                s_cn[c] = make_float4(m*nx, m*ny, m*nz, m);
            }
        }
    }
    __syncthreads();

    // ---- Final: sum_ij m_i m_j (n_i.n_j) = |sum m n|^2 ; mask.sum = (sum m)^2 ----
    if (tid < 32) {
        float sx = 0.0f, sy = 0.0f, sz = 0.0f, sc = 0.0f;
        if (tid < 10) {
            float4 v = s_cn[tid];
            sx = v.x; sy = v.y; sz = v.z; sc = v.w;
        }
        #pragma unroll
        for (int off = 16; off; off >>= 1) {
            sx += __shfl_xor_sync(0xffffffffu, sx, off);
            sy += __shfl_xor_sync(0xffffffffu, sy, off);
            sz += __shfl_xor_sync(0xffffffffu, sz, off);
            sc += __shfl_xor_sync(0xffffffffu, sc, off);
        }
        if (tid == 0)
            g_acc[b] = make_float2(sx*sx + sy*sy + sz*sz, sc*sc);
    }
}

__global__ __launch_bounds__(1024) void affinity_reduce(int bs, float* __restrict__ out)
{
    __shared__ float2 sh[32];
    int tid = threadIdx.x;
    int lane = tid & 31;
    int warp = tid >> 5;
    float a = 0.0f, c = 0.0f;
    for (int i = tid; i < bs; i += 1024) {
        float2 v = g_acc[i];
        a += v.x; c += v.y;
    }
    #pragma unroll
    for (int off = 16; off; off >>= 1) {
        a += __shfl_xor_sync(0xffffffffu, a, off);
        c += __shfl_xor_sync(0xffffffffu, c, off);
    }
    if (lane == 0) sh[warp] = make_float2(a, c);
    __syncthreads();
    if (tid < 32) {
        float2 v = sh[tid];
        a = v.x; c = v.y;
        #pragma unroll
        for (int off = 16; off; off >>= 1) {
            a += __shfl_xor_sync(0xffffffffu, a, off);
            c += __shfl_xor_sync(0xffffffffu, c, off);
        }
        if (tid == 0) out[0] = a / (c + 1.0f);
    }
}

extern "C" void kernel_launch(void* const* d_in, const int* in_sizes, int n_in,
                              void* d_out, int out_size)
{
    const float* poses = (const float*)d_in[0];
    int bs = in_sizes[0] / 87;
    if (bs > MAXB) bs = MAXB;
    affinity_main<<<bs, 128>>>(poses);
    affinity_reduce<<<1, 1024>>>(bs, (float*)d_out);
}

// round 4
// speedup vs baseline: 1.3472x; 1.0533x over previous
#include <cuda_runtime.h>
#include <math_constants.h>

#define NG      121
#define NHAND   21
#define NPAIR   126   // 21*6
#define NOBJ    726   // 6*121
#define MAXB    8192

__device__ __align__(16) float2 g_acc[MAXB];   // (num, cnt) per batch
__device__ unsigned int g_sem = 0;             // returns to 0 at end of every launch

// g = yy - 2*zz. Must be bit-identical in phase B (min) and phase D (argmin match).
__device__ __forceinline__ float gval(float hx, float hy, float hz, float4 c)
{
    return fmaf(hx, c.x, fmaf(hy, c.y, fmaf(hz, c.z, c.w)));
}

__global__ __launch_bounds__(128) void affinity_main(const float* __restrict__ poses,
                                                     float* __restrict__ out, int bs)
{
    const int b    = blockIdx.x;
    const int tid  = threadIdx.x;
    const int lane = tid & 31;
    const int warp = tid >> 5;
    const float* __restrict__ P = poses + b * 87;

    __shared__ float  s_pose[87];     // 21 hand + 8 obj, xyz
    __shared__ float  s_xx[NHAND];
    __shared__ float4 s_pts[NOBJ];    // (-2x, -2y, -2z, yy)
    __shared__ float  s_key[NPAIR];   // d2min = xx + gmin, flat = h*6+f
    __shared__ float  s_gb[NPAIR];    // exact gmin for argmin recovery
    __shared__ int    s_self[10];
    __shared__ float  s_seld[10];     // selected keys (d2min)
    __shared__ float4 s_cn[10];       // (m*nx, m*ny, m*nz, m)
    __shared__ float2 s_red[4];
    __shared__ int    s_flag;

    if (tid < 87) s_pose[tid] = P[tid];
    __syncthreads();

    if (tid < NHAND) {
        float x = s_pose[tid*3], y = s_pose[tid*3+1], z = s_pose[tid*3+2];
        s_xx[tid] = x*x + y*y + z*z;
    }

    const float* O = s_pose + NHAND*3;   // obj corners, 8 x 3

    // ---- Phase A: thread-per-gridpoint, 6 faces unrolled with literal corners ----
    if (tid < NG) {
        int iu = tid / 11;
        int iv = tid - iu * 11;
        float u = iu * 0.1f;
        float v = iv * 0.1f;
        float w0 = v * (1.0f - u);
        float w1 = v * u;
        float w2 = (1.0f - v) * (1.0f - u);
        float w3 = u * (1.0f - v);
        float Ox[8], Oy[8], Oz[8];
        #pragma unroll
        for (int k = 0; k < 8; k++) { Ox[k] = O[k*3]; Oy[k] = O[k*3+1]; Oz[k] = O[k*3+2]; }
        #define DOFACE(F, C0, C1, C2, C3) { \
            float x = w0*Ox[C0] + w1*Ox[C1] + w2*Ox[C2] + w3*Ox[C3]; \
            float y = w0*Oy[C0] + w1*Oy[C1] + w2*Oy[C2] + w3*Oy[C3]; \
            float z = w0*Oz[C0] + w1*Oz[C1] + w2*Oz[C2] + w3*Oz[C3]; \
            float yy = x*x + y*y + z*z; \
            s_pts[(F)*NG + tid] = make_float4(-2.0f*x, -2.0f*y, -2.0f*z, yy); }
        DOFACE(0, 0,1,2,3)
        DOFACE(1, 0,4,2,6)
        DOFACE(2, 0,1,4,5)
        DOFACE(3, 1,3,5,7)
        DOFACE(4, 2,3,6,7)
        DOFACE(5, 4,5,6,7)
        #undef DOFACE
    }
    __syncthreads();

    // ---- Phase B: min of g over 121 points per (h,f): LDS + 3 FMA + FMNMX ----
    if (tid < NPAIR) {
        int f = tid / NHAND;        // 0..5
        int h = tid - f * NHAND;    // 0..20
        float hx = s_pose[h*3], hy = s_pose[h*3+1], hz = s_pose[h*3+2];
        const float4* __restrict__ q = s_pts + f * NG;
        float best = CUDART_INF_F;
        #pragma unroll 11
        for (int p = 0; p < NG; p++)
            best = fminf(best, gval(hx, hy, hz, q[p]));
        s_gb [h*6 + f] = best;                        // exact min of g
        s_key[h*6 + f] = __fadd_rn(s_xx[h], best);    // d2min (monotone in g)
    }
    __syncthreads();

    // ---- Phase C: stable 10-smallest of the 126 keys (warp 0) ----
    if (tid < 32) {
        float v0[4]; int i0[4];
        #pragma unroll
        for (int k = 0; k < 4; k++) {
            int t = tid + 32*k;
            if (t < NPAIR) { v0[k] = s_key[t]; i0[k] = t; }
            else           { v0[k] = CUDART_INF_F; i0[k] = 1 << 20; }
        }
        #pragma unroll
        for (int r = 0; r < 10; r++) {
            float bv = v0[0]; int bi = i0[0];
            #pragma unroll
            for (int k = 1; k < 4; k++)
                if (v0[k] < bv || (v0[k] == bv && i0[k] < bi)) { bv = v0[k]; bi = i0[k]; }
            #pragma unroll
            for (int off = 16; off; off >>= 1) {
                float ov = __shfl_xor_sync(0xffffffffu, bv, off);
                int   oi = __shfl_xor_sync(0xffffffffu, bi, off);
                if (ov < bv || (ov == bv && oi < bi)) { bv = ov; bi = oi; }
            }
            if (r == tid) { s_self[r] = bi; s_seld[r] = bv; }
            #pragma unroll
            for (int k = 0; k < 4; k++)
                if (i0[k] == bi) v0[k] = CUDART_INF_F;
        }
    }
    __syncthreads();

    // ---- Phase D: argmin recovery by exact-match ballot + normal contribution ----
    {
        float p1x = (O[0]  + O[3]  + O[6]  + O[9] ) * 0.25f;
        float p1y = (O[1]  + O[4]  + O[7]  + O[10]) * 0.25f;
        float p1z = (O[2]  + O[5]  + O[8]  + O[11]) * 0.25f;
        float p2x = (O[12] + O[15] + O[18] + O[21]) * 0.25f;
        float p2y = (O[13] + O[16] + O[19] + O[22]) * 0.25f;
        float p2z = (O[14] + O[17] + O[20] + O[23]) * 0.25f;

        float l1 = 0.0f, l2 = 0.0f;
        #pragma unroll
        for (int e = 0; e < 4; e++) {
            int a = e, bb = (e + 1) & 3;
            float dx = O[a*3+0] - O[bb*3+0];
            float dy = O[a*3+1] - O[bb*3+1];
            float dz = O[a*3+2] - O[bb*3+2];
            l1 += sqrtf(dx*dx + dy*dy + dz*dz);
            int a2 = a + 4, b2 = bb + 4;
            dx = O[a2*3+0] - O[b2*3+0];
            dy = O[a2*3+1] - O[b2*3+1];
            dz = O[a2*3+2] - O[b2*3+2];
            l2 += sqrtf(dx*dx + dy*dy + dz*dz);
        }
        l1 *= 0.25f; l2 *= 0.25f;
        float thr = ((l1 + l2) * 0.5f) * 0.2f;

        float dvx = p2x - p1x, dvy = p2y - p1y, dvz = p2z - p1z;
        float dvn = sqrtf(dvx*dvx + dvy*dvy + dvz*dvz);
        float dvn_e = dvn + 1e-5f;
        float ndx = dvx / dvn_e, ndy = dvy / dvn_e, ndz = dvz / dvn_e;

        for (int c = warp; c < 10; c += 4) {
            int flat = s_self[c];
            int h = flat / 6;
            int f = flat - h * 6;
            float hx = s_pose[h*3], hy = s_pose[h*3+1], hz = s_pose[h*3+2];
            float gb = s_gb[flat];
            const float4* __restrict__ q = s_pts + f * NG;

            int p = 0;
            #pragma unroll
            for (int k = 0; k < 4; k++) {
                int pp = k*32 + lane;
                bool hit = (pp < NG) && (gval(hx, hy, hz, q[pp]) == gb);
                unsigned m = __ballot_sync(0xffffffffu, hit);
                if (m) { p = k*32 + (__ffs(m) - 1); break; }   // first occurrence
            }

            if (lane == 0) {
                float4 c4 = q[p];
                float cx = -0.5f * c4.x;   // exact recovery of coords
                float cy = -0.5f * c4.y;
                float cz = -0.5f * c4.z;
                float vx = cx - p1x, vy = cy - p1y, vz = cz - p1z;
                float inner = dvx*vx + dvy*vy + dvz*vz;
                float tt = inner / dvn_e;
                float rx = p1x + ndx * tt;
                float ry = p1y + ndy * tt;
                float rz = p1z + ndz * tt;
                float nx = cx - rx, ny = cy - ry, nz = cz - rz;
                float nn = sqrtf(nx*nx + ny*ny + nz*nz) + 1e-5f;
                nx /= nn; ny /= nn; nz /= nn;
                float dist = sqrtf(s_seld[c] + 1e-6f);
                float m = (dist < thr) ? 1.0f : 0.0f;
                s_cn[c] = make_float4(m*nx, m*ny, m*nz, m);
            }
        }
    }
    __syncthreads();

    // ---- Per-batch result: |sum m n|^2 and (sum m)^2 ----
    if (tid < 32) {
        float sx = 0.0f, sy = 0.0f, sz = 0.0f, sc = 0.0f;
        if (tid < 10) {
            float4 v = s_cn[tid];
            sx = v.x; sy = v.y; sz = v.z; sc = v.w;
        }
        #pragma unroll
        for (int off = 16; off; off >>= 1) {
            sx += __shfl_xor_sync(0xffffffffu, sx, off);
            sy += __shfl_xor_sync(0xffffffffu, sy, off);
            sz += __shfl_xor_sync(0xffffffffu, sz, off);
            sc += __shfl_xor_sync(0xffffffffu, sc, off);
        }
        if (tid == 0) {
            g_acc[b] = make_float2(sx*sx + sy*sy + sz*sz, sc*sc);
            __threadfence();                       // release g_acc[b]
            unsigned old = atomicAdd(&g_sem, 1u);
            s_flag = (old == (unsigned)(bs - 1));
        }
    }
    __syncthreads();

    // ---- Last block: deterministic final reduction, semaphore self-reset ----
    if (s_flag) {
        __threadfence();                           // acquire all g_acc
        float a = 0.0f, c = 0.0f;
        const float4* __restrict__ A = (const float4*)g_acc;
        int n4 = bs >> 1;
        for (int i = tid; i < n4; i += 128) {
            float4 v = A[i];
            a += v.x + v.z;
            c += v.y + v.w;
        }
        if ((bs & 1) && tid == 0) { float2 v = g_acc[bs - 1]; a += v.x; c += v.y; }
        #pragma unroll
        for (int off = 16; off; off >>= 1) {
            a += __shfl_xor_sync(0xffffffffu, a, off);
            c += __shfl_xor_sync(0xffffffffu, c, off);
        }
        if (lane == 0) s_red[warp] = make_float2(a, c);
        __syncthreads();
        if (tid == 0) {
            a = s_red[0].x + s_red[1].x + s_red[2].x + s_red[3].x;
            c = s_red[0].y + s_red[1].y + s_red[2].y + s_red[3].y;
            out[0] = a / (c + 1.0f);
            atomicExch(&g_sem, 0u);                // reset for next graph replay
        }
    }
}

extern "C" void kernel_launch(void* const* d_in, const int* in_sizes, int n_in,
                              void* d_out, int out_size)
{
    const float* poses = (const float*)d_in[0];
    int bs = in_sizes[0] / 87;
    if (bs > MAXB) bs = MAXB;
    affinity_main<<<bs, 128>>>(poses, (float*)d_out, bs);
}

// round 5
// speedup vs baseline: 1.3744x; 1.0202x over previous
#include <cuda_runtime.h>
#include <math_constants.h>

#define NG      121
#define NHAND   21
#define NPAIR   126   // 21*6
#define NOBJ    726   // 6*121
#define MAXB    8192

__device__ __align__(16) float2 g_acc[MAXB];   // (num, cnt) per batch
__device__ unsigned int g_sem = 0;             // returns to 0 at end of every launch

// g = yy - 2*zz. Must be bit-identical in phase B (min) and phase D (argmin match).
__device__ __forceinline__ float gval(float hx, float hy, float hz, float4 c)
{
    return fmaf(hx, c.x, fmaf(hy, c.y, fmaf(hz, c.z, c.w)));
}

__global__ __launch_bounds__(128) void affinity_main(const float* __restrict__ poses,
                                                     float* __restrict__ out, int bs)
{
    const int b    = blockIdx.x;
    const int tid  = threadIdx.x;
    const int lane = tid & 31;
    const int warp = tid >> 5;
    const float* __restrict__ P = poses + b * 87;

    __shared__ float  s_pose[87];     // 21 hand + 8 obj, xyz
    __shared__ float  s_xx[NHAND];
    __shared__ float4 s_pts[NOBJ];    // (-2x, -2y, -2z, yy)
    __shared__ float  s_key[NPAIR];   // d2min = xx + gmin, flat = h*6+f
    __shared__ float  s_gb[NPAIR];    // exact gmin for argmin recovery
    __shared__ int    s_self[10];
    __shared__ float  s_seld[10];     // selected keys (d2min)
    __shared__ float4 s_cn[10];       // (m*nx, m*ny, m*nz, m)
    __shared__ float  s_geo[11];      // p1(3) dv(3) nd(3) dvn_e thr
    __shared__ float2 s_red[4];
    __shared__ int    s_flag;

    if (tid < 87) s_pose[tid] = P[tid];
    __syncthreads();

    if (tid < NHAND) {
        float x = s_pose[tid*3], y = s_pose[tid*3+1], z = s_pose[tid*3+2];
        s_xx[tid] = x*x + y*y + z*z;
    }

    const float* O = s_pose + NHAND*3;   // obj corners, 8 x 3

    // ---- Phase A: thread-per-gridpoint, 6 faces unrolled with literal corners ----
    if (tid < NG) {
        int iu = tid / 11;
        int iv = tid - iu * 11;
        float u = iu * 0.1f;
        float v = iv * 0.1f;
        float w0 = v * (1.0f - u);
        float w1 = v * u;
        float w2 = (1.0f - v) * (1.0f - u);
        float w3 = u * (1.0f - v);
        float Ox[8], Oy[8], Oz[8];
        #pragma unroll
        for (int k = 0; k < 8; k++) { Ox[k] = O[k*3]; Oy[k] = O[k*3+1]; Oz[k] = O[k*3+2]; }
        #define DOFACE(F, C0, C1, C2, C3) { \
            float x = w0*Ox[C0] + w1*Ox[C1] + w2*Ox[C2] + w3*Ox[C3]; \
            float y = w0*Oy[C0] + w1*Oy[C1] + w2*Oy[C2] + w3*Oy[C3]; \
            float z = w0*Oz[C0] + w1*Oz[C1] + w2*Oz[C2] + w3*Oz[C3]; \
            float yy = x*x + y*y + z*z; \
            s_pts[(F)*NG + tid] = make_float4(-2.0f*x, -2.0f*y, -2.0f*z, yy); }
        DOFACE(0, 0,1,2,3)
        DOFACE(1, 0,4,2,6)
        DOFACE(2, 0,1,4,5)
        DOFACE(3, 1,3,5,7)
        DOFACE(4, 2,3,6,7)
        DOFACE(5, 4,5,6,7)
        #undef DOFACE
    }
    __syncthreads();

    // ---- Phase B: min of g over 121 points per (h,f), 4 independent accumulators ----
    if (tid < NPAIR) {
        int f = tid / NHAND;        // 0..5
        int h = tid - f * NHAND;    // 0..20
        float hx = s_pose[h*3], hy = s_pose[h*3+1], hz = s_pose[h*3+2];
        const float4* __restrict__ q = s_pts + f * NG;
        float b0 = CUDART_INF_F, b1 = CUDART_INF_F, b2 = CUDART_INF_F, b3 = CUDART_INF_F;
        #pragma unroll 5
        for (int p = 0; p < 30; p++) {
            b0 = fminf(b0, gval(hx, hy, hz, q[4*p+0]));
            b1 = fminf(b1, gval(hx, hy, hz, q[4*p+1]));
            b2 = fminf(b2, gval(hx, hy, hz, q[4*p+2]));
            b3 = fminf(b3, gval(hx, hy, hz, q[4*p+3]));
        }
        b0 = fminf(b0, gval(hx, hy, hz, q[120]));
        float best = fminf(fminf(b0, b1), fminf(b2, b3));   // min exactly assoc/comm
        s_gb [h*6 + f] = best;                        // exact min of g
        s_key[h*6 + f] = __fadd_rn(s_xx[h], best);    // d2min (monotone in g)
    }
    __syncthreads();

    // ---- Phase C (warp 0): stable 10-smallest of the 126 keys
    //      Overlapped: warp 1 computes contact geometry into s_geo ----
    if (warp == 0) {
        float v0[4]; int i0[4];
        #pragma unroll
        for (int k = 0; k < 4; k++) {
            int t = tid + 32*k;
            if (t < NPAIR) { v0[k] = s_key[t]; i0[k] = t; }
            else           { v0[k] = CUDART_INF_F; i0[k] = 1 << 20; }
        }
        #pragma unroll
        for (int r = 0; r < 10; r++) {
            float bv = v0[0]; int bi = i0[0];
            #pragma unroll
            for (int k = 1; k < 4; k++)
                if (v0[k] < bv || (v0[k] == bv && i0[k] < bi)) { bv = v0[k]; bi = i0[k]; }
            #pragma unroll
            for (int off = 16; off; off >>= 1) {
                float ov = __shfl_xor_sync(0xffffffffu, bv, off);
                int   oi = __shfl_xor_sync(0xffffffffu, bi, off);
                if (ov < bv || (ov == bv && oi < bi)) { bv = ov; bi = oi; }
            }
            if (r == tid) { s_self[r] = bi; s_seld[r] = bv; }
            #pragma unroll
            for (int k = 0; k < 4; k++)
                if (i0[k] == bi) v0[k] = CUDART_INF_F;
        }
    } else if (warp == 1) {
        float p1x = (O[0]  + O[3]  + O[6]  + O[9] ) * 0.25f;
        float p1y = (O[1]  + O[4]  + O[7]  + O[10]) * 0.25f;
        float p1z = (O[2]  + O[5]  + O[8]  + O[11]) * 0.25f;
        float p2x = (O[12] + O[15] + O[18] + O[21]) * 0.25f;
        float p2y = (O[13] + O[16] + O[19] + O[22]) * 0.25f;
        float p2z = (O[14] + O[17] + O[20] + O[23]) * 0.25f;

        float l1 = 0.0f, l2 = 0.0f;
        #pragma unroll
        for (int e = 0; e < 4; e++) {
            int a = e, bb = (e + 1) & 3;
            float dx = O[a*3+0] - O[bb*3+0];
            float dy = O[a*3+1] - O[bb*3+1];
            float dz = O[a*3+2] - O[bb*3+2];
            l1 += sqrtf(dx*dx + dy*dy + dz*dz);
            int a2 = a + 4, b2 = bb + 4;
            dx = O[a2*3+0] - O[b2*3+0];
            dy = O[a2*3+1] - O[b2*3+1];
            dz = O[a2*3+2] - O[b2*3+2];
            l2 += sqrtf(dx*dx + dy*dy + dz*dz);
        }
        l1 *= 0.25f; l2 *= 0.25f;
        float thr = ((l1 + l2) * 0.5f) * 0.2f;

        float dvx = p2x - p1x, dvy = p2y - p1y, dvz = p2z - p1z;
        float dvn = sqrtf(dvx*dvx + dvy*dvy + dvz*dvz);
        float dvn_e = dvn + 1e-5f;

        if (lane == 0) {
            s_geo[0] = p1x; s_geo[1] = p1y; s_geo[2] = p1z;
            s_geo[3] = dvx; s_geo[4] = dvy; s_geo[5] = dvz;
            s_geo[6] = dvx / dvn_e; s_geo[7] = dvy / dvn_e; s_geo[8] = dvz / dvn_e;
            s_geo[9] = dvn_e; s_geo[10] = thr;
        }
    }
    __syncthreads();

    // ---- Phase D: argmin recovery by exact-match ballot + normal contribution ----
    {
        float p1x = s_geo[0], p1y = s_geo[1], p1z = s_geo[2];
        float dvx = s_geo[3], dvy = s_geo[4], dvz = s_geo[5];
        float ndx = s_geo[6], ndy = s_geo[7], ndz = s_geo[8];
        float dvn_e = s_geo[9], thr = s_geo[10];

        for (int c = warp; c < 10; c += 4) {
            int flat = s_self[c];
            int h = flat / 6;
            int f = flat - h * 6;
            float hx = s_pose[h*3], hy = s_pose[h*3+1], hz = s_pose[h*3+2];
            float gb = s_gb[flat];
            const float4* __restrict__ q = s_pts + f * NG;

            int p = 0;
            #pragma unroll
            for (int k = 0; k < 4; k++) {
                int pp = k*32 + lane;
                bool hit = (pp < NG) && (gval(hx, hy, hz, q[pp]) == gb);
                unsigned m = __ballot_sync(0xffffffffu, hit);
                if (m) { p = k*32 + (__ffs(m) - 1); break; }   // first occurrence
            }

            if (lane == 0) {
                float4 c4 = q[p];
                float cx = -0.5f * c4.x;   // exact recovery of coords
                float cy = -0.5f * c4.y;
                float cz = -0.5f * c4.z;
                float vx = cx - p1x, vy = cy - p1y, vz = cz - p1z;
                float inner = dvx*vx + dvy*vy + dvz*vz;
                float tt = inner / dvn_e;
                float rx = p1x + ndx * tt;
                float ry = p1y + ndy * tt;
                float rz = p1z + ndz * tt;
                float nx = cx - rx, ny = cy - ry, nz = cz - rz;
                float nn = sqrtf(nx*nx + ny*ny + nz*nz) + 1e-5f;
                nx /= nn; ny /= nn; nz /= nn;
                float dist = sqrtf(s_seld[c] + 1e-6f);
                float m = (dist < thr) ? 1.0f : 0.0f;
                s_cn[c] = make_float4(m*nx, m*ny, m*nz, m);
            }
        }
    }
    __syncthreads();

    // ---- Per-batch result: |sum m n|^2 and (sum m)^2 ----
    if (tid < 32) {
        float sx = 0.0f, sy = 0.0f, sz = 0.0f, sc = 0.0f;
        if (tid < 10) {
            float4 v = s_cn[tid];
            sx = v.x; sy = v.y; sz = v.z; sc = v.w;
        }
        #pragma unroll
        for (int off = 16; off; off >>= 1) {
            sx += __shfl_xor_sync(0xffffffffu, sx, off);
            sy += __shfl_xor_sync(0xffffffffu, sy, off);
            sz += __shfl_xor_sync(0xffffffffu, sz, off);
            sc += __shfl_xor_sync(0xffffffffu, sc, off);
        }
        if (tid == 0) {
            g_acc[b] = make_float2(sx*sx + sy*sy + sz*sz, sc*sc);
            __threadfence();                       // release g_acc[b]
            unsigned old = atomicAdd(&g_sem, 1u);
            s_flag = (old == (unsigned)(bs - 1));
        }
    }
    __syncthreads();

    // ---- Last block: deterministic final reduction, semaphore self-reset ----
    if (s_flag) {
        __threadfence();                           // acquire all g_acc
        float a = 0.0f, c = 0.0f;
        const float4* __restrict__ A = (const float4*)g_acc;
        int n4 = bs >> 1;
        for (int i = tid; i < n4; i += 128) {
            float4 v = A[i];
            a += v.x + v.z;
            c += v.y + v.w;
        }
        if ((bs & 1) && tid == 0) { float2 v = g_acc[bs - 1]; a += v.x; c += v.y; }
        #pragma unroll
        for (int off = 16; off; off >>= 1) {
            a += __shfl_xor_sync(0xffffffffu, a, off);
            c += __shfl_xor_sync(0xffffffffu, c, off);
        }
        if (lane == 0) s_red[warp] = make_float2(a, c);
        __syncthreads();
        if (tid == 0) {
            a = s_red[0].x + s_red[1].x + s_red[2].x + s_red[3].x;
            c = s_red[0].y + s_red[1].y + s_red[2].y + s_red[3].y;
            out[0] = a / (c + 1.0f);
            atomicExch(&g_sem, 0u);                // reset for next graph replay
        }
    }
}

extern "C" void kernel_launch(void* const* d_in, const int* in_sizes, int n_in,
                              void* d_out, int out_size)
{
    const float* poses = (const float*)d_in[0];
    int bs = in_sizes[0] / 87;
    if (bs > MAXB) bs = MAXB;
    affinity_main<<<bs, 128>>>(poses, (float*)d_out, bs);
}